// round 15
// baseline (speedup 1.0000x reference)
#include <cuda_runtime.h>
#include <float.h>

typedef unsigned long long ull;
#define FULLMASK 0xFFFFFFFFu
#define NBLK 296
#define WROW 516   // float2 per w_d row

// ---------------------------------------------------------------------------
// MID_LOSS: B=8192, E=512, M=8, C=14, BETA=0.3
// x [B, E*M] f32 (m contiguous per e), y [B,C] i32, w [E,C] f32
// One kernel, warp-autonomous. 296 blocks x 256 thr, 16 warps/SM.
// Lane = (ch, es): ch = lane>>4 owns classes ch*7..ch*7+6;
// es = lane&15 owns embed PAIRS e = {2es, 2es+1} + 32*i, i in [0,16).
// acc packed over m-pairs; per class one LDS.128 serves both e's (dup w).
// ---------------------------------------------------------------------------

static __device__ float g_partials[NBLK];
static __device__ unsigned g_counter = 0;

__device__ __forceinline__ ull ffma2(ull a, ull b, ull c) {
    ull d; asm("fma.rn.f32x2 %0, %1, %2, %3;" : "=l"(d) : "l"(a), "l"(b), "l"(c));
    return d;
}
__device__ __forceinline__ void upk(ull v, float& lo, float& hi) {
    asm("mov.b64 {%0, %1}, %2;" : "=f"(lo), "=f"(hi) : "l"(v));
}
__device__ __forceinline__ float softplus_f(float v) {
    return fmaxf(v, 0.0f) + log1pf(expf(-fabsf(v)));
}

__global__ __launch_bounds__(256, 2)
void main_kernel(const float* __restrict__ x, const int* __restrict__ y,
                 const float* __restrict__ w, float* __restrict__ out) {
    extern __shared__ __align__(16) float2 w_d[];   // [14][WROW], (w,w) pairs
    __shared__ float gram_s[196];
    __shared__ float dot_s[8][112];   // per-warp [c*8+m]
    __shared__ float dc_s[8][16];
    __shared__ float l1_s[8][2];
    __shared__ float wpart[8];
    __shared__ int lastflag;

    const int tid  = threadIdx.x;
    const int lane = tid & 31;
    const int wid  = tid >> 5;
    const int es   = lane & 15;
    const int ch   = lane >> 4;

    // ---- stage w duplicated: w_d[c][e] = (w[e,c], w[e,c]) ----
    for (int i = tid; i < 7168; i += 256) {
        int e = i / 14, c = i - e * 14;
        float v = w[i];
        w_d[c * WROW + e] = make_float2(v, v);
    }
    __syncthreads();

    // ---- fused Gram: 105 symmetric pairs over 8 warps ----
    {
        int p = 0;
        for (int c = 0; c < 14; ++c)
            for (int c2 = c; c2 < 14; ++c2, ++p) {
                if ((p & 7) != wid) continue;
                float sd = 0.0f;
                #pragma unroll
                for (int k = 0; k < 16; ++k) {
                    int e = lane + 32 * k;
                    sd += w_d[c * WROW + e].x * w_d[c2 * WROW + e].x;
                }
                #pragma unroll
                for (int o = 16; o; o >>= 1) sd += __shfl_xor_sync(FULLMASK, sd, o);
                if (lane == 0) { gram_s[c * 14 + c2] = sd; gram_s[c2 * 14 + c] = sd; }
            }
    }
    __syncthreads();   // hot loop below is warp-local

    const int gwarp = blockIdx.x * 8 + wid;
    const int bidx = __brev((unsigned)es) >> 28;
    float wsum = 0.0f;

    for (int s = gwarp; s < 8192; s += 2368) {
        const int yv = (lane < 14) ? y[s * 14 + lane] : 0;

        ull acc[7][4];   // [ci][m-pair]
        #pragma unroll
        for (int ci = 0; ci < 7; ++ci)
            #pragma unroll
            for (int mp = 0; mp < 4; ++mp) acc[ci][mp] = 0ull;
        float l1 = 0.0f;

        // lane stream: step i covers float4 idx 4es+64i .. +3 (e0 m0..7, e1 m0..7)
        const float4* xs = (const float4*)(x + (size_t)s * 4096) + 4 * es;
        float4 buf[2][4];
        #pragma unroll
        for (int j = 0; j < 4; ++j) buf[0][j] = __ldcs(xs + j);
        #pragma unroll
        for (int j = 0; j < 4; ++j) buf[1][j] = __ldcs(xs + 64 + j);

        const float2* wp = w_d + ch * 7 * WROW + 2 * es;

        #pragma unroll
        for (int i = 0; i < 16; ++i) {
            const ull* pv = (const ull*)buf[i & 1];   // [0..3]=e0 m-pairs, [4..7]=e1

            // GEMM: 7 classes, one LDS.128 per class serves both e's
            const float2* wr = wp + i * 32;
            #pragma unroll
            for (int ci = 0; ci < 7; ++ci) {
                longlong2 wv = *(const longlong2*)(wr + ci * WROW);
                const ull w0 = (ull)wv.x, w1 = (ull)wv.y;
                acc[ci][0] = ffma2(pv[0], w0, acc[ci][0]);
                acc[ci][1] = ffma2(pv[1], w0, acc[ci][1]);
                acc[ci][2] = ffma2(pv[2], w0, acc[ci][2]);
                acc[ci][3] = ffma2(pv[3], w0, acc[ci][3]);
                acc[ci][0] = ffma2(pv[4], w1, acc[ci][0]);
                acc[ci][1] = ffma2(pv[5], w1, acc[ci][1]);
                acc[ci][2] = ffma2(pv[6], w1, acc[ci][2]);
                acc[ci][3] = ffma2(pv[7], w1, acc[ci][3]);
            }

            // l1: unbiased var over m for e0 and e1 (lane-local)
            #pragma unroll
            for (int h = 0; h < 2; ++h) {
                float s0, s1, s2, s3, t0, t1, t2, t3;
                upk(pv[4 * h + 0], s0, s1);
                upk(pv[4 * h + 1], s2, s3);
                upk(pv[4 * h + 2], t0, t1);
                upk(pv[4 * h + 3], t2, t3);
                const float se = ((s0 + s1) + (s2 + s3)) + ((t0 + t1) + (t2 + t3));
                float qe = s0 * s0;
                qe = fmaf(s1, s1, qe); qe = fmaf(s2, s2, qe); qe = fmaf(s3, s3, qe);
                qe = fmaf(t0, t0, qe); qe = fmaf(t1, t1, qe);
                qe = fmaf(t2, t2, qe); qe = fmaf(t3, t3, qe);
                const float var = fmaf(se * se, -1.0f / 56.0f, qe * (1.0f / 7.0f));
                l1 += fabsf(var);
            }

            // refill this buffer for step i+2 (after last use of pv)
            if (i + 2 < 16) {
                #pragma unroll
                for (int j = 0; j < 4; ++j)
                    buf[i & 1][j] = __ldcs(xs + 64 * (i + 2) + j);
            }
        }

        // ---- Pass A: reduce 32 values (ci 0..3) over the 16-lane ch group ----
        {
            float a[32];
            #pragma unroll
            for (int ci = 0; ci < 4; ++ci)
                #pragma unroll
                for (int mp = 0; mp < 4; ++mp)
                    upk(acc[ci][mp], a[(ci * 4 + mp) * 2], a[(ci * 4 + mp) * 2 + 1]);

            float t16[16];
            #pragma unroll
            for (int j = 0; j < 16; ++j) {
                bool h = (lane & 8) != 0;
                float snd = h ? a[2 * j] : a[2 * j + 1];
                float kp  = h ? a[2 * j + 1] : a[2 * j];
                t16[j] = kp + __shfl_xor_sync(FULLMASK, snd, 8);
            }
            float t8[8];
            #pragma unroll
            for (int j = 0; j < 8; ++j) {
                bool h = (lane & 4) != 0;
                float snd = h ? t16[2 * j] : t16[2 * j + 1];
                float kp  = h ? t16[2 * j + 1] : t16[2 * j];
                t8[j] = kp + __shfl_xor_sync(FULLMASK, snd, 4);
            }
            float t4[4];
            #pragma unroll
            for (int j = 0; j < 4; ++j) {
                bool h = (lane & 2) != 0;
                float snd = h ? t8[2 * j] : t8[2 * j + 1];
                float kp  = h ? t8[2 * j + 1] : t8[2 * j];
                t4[j] = kp + __shfl_xor_sync(FULLMASK, snd, 2);
            }
            float t2[2];
            #pragma unroll
            for (int j = 0; j < 2; ++j) {
                bool h = (lane & 1) != 0;
                float snd = h ? t4[2 * j] : t4[2 * j + 1];
                float kp  = h ? t4[2 * j + 1] : t4[2 * j];
                t2[j] = kp + __shfl_xor_sync(FULLMASK, snd, 1);
            }
            #pragma unroll
            for (int t = 0; t < 2; ++t) {
                int idx = t * 16 + bidx;        // value index in [0,32)
                int k = idx >> 1;
                int ci = k >> 2, mp = k & 3;
                int m = 2 * mp + (idx & 1);
                dot_s[wid][(ch * 7 + ci) * 8 + m] = t2[t];
            }
        }

        // ---- Pass B: reduce 32 values (ci 4..6 + l1) ----
        {
            float a[32];
            #pragma unroll
            for (int ci = 0; ci < 3; ++ci)
                #pragma unroll
                for (int mp = 0; mp < 4; ++mp)
                    upk(acc[4 + ci][mp], a[(ci * 4 + mp) * 2], a[(ci * 4 + mp) * 2 + 1]);
            a[24] = l1;
            #pragma unroll
            for (int j = 25; j < 32; ++j) a[j] = 0.0f;

            float t16[16];
            #pragma unroll
            for (int j = 0; j < 16; ++j) {
                bool h = (lane & 8) != 0;
                float snd = h ? a[2 * j] : a[2 * j + 1];
                float kp  = h ? a[2 * j + 1] : a[2 * j];
                t16[j] = kp + __shfl_xor_sync(FULLMASK, snd, 8);
            }
            float t8[8];
            #pragma unroll
            for (int j = 0; j < 8; ++j) {
                bool h = (lane & 4) != 0;
                float snd = h ? t16[2 * j] : t16[2 * j + 1];
                float kp  = h ? t16[2 * j + 1] : t16[2 * j];
                t8[j] = kp + __shfl_xor_sync(FULLMASK, snd, 4);
            }
            float t4[4];
            #pragma unroll
            for (int j = 0; j < 4; ++j) {
                bool h = (lane & 2) != 0;
                float snd = h ? t8[2 * j] : t8[2 * j + 1];
                float kp  = h ? t8[2 * j + 1] : t8[2 * j];
                t4[j] = kp + __shfl_xor_sync(FULLMASK, snd, 2);
            }
            float t2[2];
            #pragma unroll
            for (int j = 0; j < 2; ++j) {
                bool h = (lane & 1) != 0;
                float snd = h ? t4[2 * j] : t4[2 * j + 1];
                float kp  = h ? t4[2 * j + 1] : t4[2 * j];
                t2[j] = kp + __shfl_xor_sync(FULLMASK, snd, 1);
            }
            #pragma unroll
            for (int t = 0; t < 2; ++t) {
                int idx = t * 16 + bidx;
                if (idx < 24) {
                    int k = idx >> 1;
                    int ci = 4 + (k >> 2), mp = k & 3;
                    int m = 2 * mp + (idx & 1);
                    dot_s[wid][(ch * 7 + ci) * 8 + m] = t2[t];
                } else if (idx == 24) {
                    l1_s[wid][ch] = t2[t];
                }
            }
        }
        __syncwarp();

        // ---- epilogue (warp-local) ----
        const bool inc = lane < 14;
        float dmax = -FLT_MAX;
        if (inc) {
            #pragma unroll
            for (int m = 0; m < 8; ++m)
                dmax = fmaxf(dmax, dot_s[wid][lane * 8 + m]);
            dc_s[wid][lane] = dmax;
        }
        const unsigned pmask = __ballot_sync(FULLMASK, inc && (yv == 1));
        const unsigned nmask = (~pmask) & 0x3FFFu;
        const int npos = __popc(pmask);
        const int nneg = __popc(nmask);
        __syncwarp();

        float sloc = 0.0f, diag = 0.0f, row = 0.0f;
        if (inc && ((pmask >> lane) & 1)) {
            if (nneg > 0) {
                #pragma unroll
                for (int n = 0; n < 14; ++n)
                    if ((nmask >> n) & 1) sloc += softplus_f(dc_s[wid][n] - dmax);
            } else {
                sloc = softplus_f(-dmax);
            }
            diag = gram_s[lane * 15];
            #pragma unroll
            for (int c2 = 0; c2 < 14; ++c2)
                if ((pmask >> c2) & 1) row += gram_s[lane * 14 + c2];
        }
        #pragma unroll
        for (int o = 16; o; o >>= 1) {
            sloc += __shfl_xor_sync(FULLMASK, sloc, o);
            diag += __shfl_xor_sync(FULLMASK, diag, o);
            row  += __shfl_xor_sync(FULLMASK, row,  o);
        }
        if (lane == 0) {
            const float npf = (float)npos;
            float tv = 0.0f;
            if (npos > 1) tv = (diag - row / npf) / (npf - 1.0f);
            const float base = sloc / npf;
            const float l1t = l1_s[wid][0];
            wsum += 2.0f * (0.7f * (1.0f + tv) * base + 0.3f * l1t);
        }
    }

    // ---- block partial + in-kernel final reduction (last block) ----
    if (lane == 0) wpart[wid] = wsum;
    __syncthreads();
    if (tid == 0) {
        float bs = wpart[0] + wpart[1] + wpart[2] + wpart[3]
                 + wpart[4] + wpart[5] + wpart[6] + wpart[7];
        g_partials[blockIdx.x] = bs;
        __threadfence();
        unsigned old = atomicAdd(&g_counter, 1u);
        lastflag = (old == NBLK - 1) ? 1 : 0;
    }
    __syncthreads();
    if (lastflag && wid == 0) {
        float vsum = 0.0f;
        for (int k = lane; k < NBLK; k += 32) vsum += __ldcg(&g_partials[k]);
        #pragma unroll
        for (int o = 16; o; o >>= 1) vsum += __shfl_xor_sync(FULLMASK, vsum, o);
        if (lane == 0) {
            out[0] = vsum * (1.0f / 8192.0f);
            g_counter = 0;   // reset for next graph replay
        }
    }
}

extern "C" void kernel_launch(void* const* d_in, const int* in_sizes, int n_in,
                              void* d_out, int out_size) {
    const float* x = (const float*)d_in[0];
    const int*   y = (const int*)d_in[1];
    const float* w = (const float*)d_in[2];

    const int dyn_smem = 14 * WROW * (int)sizeof(float2);   // 57,792 B
    cudaFuncSetAttribute(main_kernel, cudaFuncAttributeMaxDynamicSharedMemorySize,
                         dyn_smem);
    main_kernel<<<NBLK, 256, dyn_smem>>>(x, y, w, (float*)d_out);
}

// round 16
// speedup vs baseline: 1.0756x; 1.0756x over previous
#include <cuda_runtime.h>
#include <float.h>

typedef unsigned long long ull;
#define FULLMASK 0xFFFFFFFFu
#define NBLK 296
#define WROW 516   // float2 per w_d row

// ---------------------------------------------------------------------------
// MID_LOSS: B=8192, E=512, M=8, C=14, BETA=0.3
// x [B, E*M] f32 (m contiguous per e), y [B,C] i32, w [E,C] f32
// One kernel, warp-autonomous. 296 blocks x 256 thr, 16 warps/SM.
// Lane = (ch, es): ch = lane>>4 owns classes ch*7..ch*7+6;
// es = lane&15 owns embeds e = es + 16*i, i in [0,32) (full m per lane).
// acc packed over m-pairs (native x layout); w duplicated (w,w) -> LDS.64.
// L2 prefetch of the warp's NEXT sample hides DRAM latency.
// ---------------------------------------------------------------------------

static __device__ float g_partials[NBLK];
static __device__ unsigned g_counter = 0;

__device__ __forceinline__ ull ffma2(ull a, ull b, ull c) {
    ull d; asm("fma.rn.f32x2 %0, %1, %2, %3;" : "=l"(d) : "l"(a), "l"(b), "l"(c));
    return d;
}
__device__ __forceinline__ void upk(ull v, float& lo, float& hi) {
    asm("mov.b64 {%0, %1}, %2;" : "=f"(lo), "=f"(hi) : "l"(v));
}
__device__ __forceinline__ float softplus_f(float v) {
    return fmaxf(v, 0.0f) + log1pf(expf(-fabsf(v)));
}

__global__ __launch_bounds__(256, 2)
void main_kernel(const float* __restrict__ x, const int* __restrict__ y,
                 const float* __restrict__ w, float* __restrict__ out) {
    extern __shared__ __align__(16) float2 w_d[];   // [14][WROW], (w,w) pairs
    __shared__ float gram_s[196];
    __shared__ float dot_s[8][112];   // per-warp [c*8+m]
    __shared__ float dc_s[8][16];
    __shared__ float l1_s[8][2];
    __shared__ float wpart[8];
    __shared__ int lastflag;

    const int tid  = threadIdx.x;
    const int lane = tid & 31;
    const int wid  = tid >> 5;
    const int es   = lane & 15;
    const int ch   = lane >> 4;

    // ---- stage w duplicated: w_d[c][e] = (w[e,c], w[e,c]) ----
    for (int i = tid; i < 7168; i += 256) {
        int e = i / 14, c = i - e * 14;
        float v = w[i];
        w_d[c * WROW + e] = make_float2(v, v);
    }
    __syncthreads();

    // ---- fused Gram: 105 symmetric pairs over 8 warps ----
    {
        int p = 0;
        for (int c = 0; c < 14; ++c)
            for (int c2 = c; c2 < 14; ++c2, ++p) {
                if ((p & 7) != wid) continue;
                float sd = 0.0f;
                #pragma unroll
                for (int k = 0; k < 16; ++k) {
                    int e = lane + 32 * k;
                    sd += w_d[c * WROW + e].x * w_d[c2 * WROW + e].x;
                }
                #pragma unroll
                for (int o = 16; o; o >>= 1) sd += __shfl_xor_sync(FULLMASK, sd, o);
                if (lane == 0) { gram_s[c * 14 + c2] = sd; gram_s[c2 * 14 + c] = sd; }
            }
    }
    __syncthreads();   // hot loop below is warp-local

    const int gwarp = blockIdx.x * 8 + wid;
    const int bidx = __brev((unsigned)es) >> 28;
    float wsum = 0.0f;

    for (int s = gwarp; s < 8192; s += 2368) {
        // ---- L2 prefetch of this warp's NEXT sample (16 KB, 4 inst) ----
        {
            const int sn = (s + 2368 < 8192) ? s + 2368 : s;
            const char* nb = (const char*)(x + (size_t)sn * 4096);
            #pragma unroll
            for (int k = 0; k < 4; ++k)
                asm volatile("prefetch.global.L2 [%0];"
                             :: "l"(nb + (lane + 32 * k) * 128));
        }

        const int yv = (lane < 14) ? y[s * 14 + lane] : 0;

        ull acc[7][4];   // [ci][m-pair]
        #pragma unroll
        for (int ci = 0; ci < 7; ++ci)
            #pragma unroll
            for (int mp = 0; mp < 4; ++mp) acc[ci][mp] = 0ull;
        float l1 = 0.0f;

        // lane's stream: per step i, embed e = es + 16i -> 32B at float4 idx 2e
        const longlong2* xp = (const longlong2*)(x + (size_t)s * 4096) + 2 * es;
        longlong2 qa[4], qb[4];   // qa=(m0..3), qb=(m4..7), depth-4 pipeline
        #pragma unroll
        for (int j = 0; j < 4; ++j) { qa[j] = xp[32 * j]; qb[j] = xp[32 * j + 1]; }

        const float2* wp = w_d + ch * 7 * WROW + es;

        for (int ib = 0; ib < 32; ib += 4) {
            #pragma unroll
            for (int j = 0; j < 4; ++j) {
                const ull p0 = (ull)qa[j].x;   // (m0,m1)
                const ull p1 = (ull)qa[j].y;   // (m2,m3)
                const ull p2 = (ull)qb[j].x;   // (m4,m5)
                const ull p3 = (ull)qb[j].y;   // (m6,m7)
                // refill slot j for step ib+4+j
                if (ib + 4 < 32) {
                    qa[j] = xp[32 * (ib + 4 + j)];
                    qb[j] = xp[32 * (ib + 4 + j) + 1];
                }
                // GEMM: 7 classes, duplicated-w LDS.64 operand
                const float2* wrow = wp + (ib + j) * 16;
                #pragma unroll
                for (int ci = 0; ci < 7; ++ci) {
                    ull w2 = *(const ull*)(wrow + ci * WROW);
                    acc[ci][0] = ffma2(p0, w2, acc[ci][0]);
                    acc[ci][1] = ffma2(p1, w2, acc[ci][1]);
                    acc[ci][2] = ffma2(p2, w2, acc[ci][2]);
                    acc[ci][3] = ffma2(p3, w2, acc[ci][3]);
                }
                // l1: unbiased var over the 8 m's of this e (lane-local)
                float s0, s1, s2, s3, t0, t1, t2, t3;
                upk(p0, s0, s1); upk(p1, s2, s3);
                upk(p2, t0, t1); upk(p3, t2, t3);
                const float se = ((s0 + s1) + (s2 + s3)) + ((t0 + t1) + (t2 + t3));
                float qe = s0 * s0;
                qe = fmaf(s1, s1, qe); qe = fmaf(s2, s2, qe); qe = fmaf(s3, s3, qe);
                qe = fmaf(t0, t0, qe); qe = fmaf(t1, t1, qe);
                qe = fmaf(t2, t2, qe); qe = fmaf(t3, t3, qe);
                const float var = fmaf(se * se, -1.0f / 56.0f, qe * (1.0f / 7.0f));
                l1 += fabsf(var);
            }
        }

        // ---- Pass A: reduce 32 values (ci 0..3) over the 16-lane ch group ----
        {
            float a[32];
            #pragma unroll
            for (int ci = 0; ci < 4; ++ci)
                #pragma unroll
                for (int mp = 0; mp < 4; ++mp)
                    upk(acc[ci][mp], a[(ci * 4 + mp) * 2], a[(ci * 4 + mp) * 2 + 1]);

            float t16[16];
            #pragma unroll
            for (int j = 0; j < 16; ++j) {
                bool h = (lane & 8) != 0;
                float snd = h ? a[2 * j] : a[2 * j + 1];
                float kp  = h ? a[2 * j + 1] : a[2 * j];
                t16[j] = kp + __shfl_xor_sync(FULLMASK, snd, 8);
            }
            float t8[8];
            #pragma unroll
            for (int j = 0; j < 8; ++j) {
                bool h = (lane & 4) != 0;
                float snd = h ? t16[2 * j] : t16[2 * j + 1];
                float kp  = h ? t16[2 * j + 1] : t16[2 * j];
                t8[j] = kp + __shfl_xor_sync(FULLMASK, snd, 4);
            }
            float t4[4];
            #pragma unroll
            for (int j = 0; j < 4; ++j) {
                bool h = (lane & 2) != 0;
                float snd = h ? t8[2 * j] : t8[2 * j + 1];
                float kp  = h ? t8[2 * j + 1] : t8[2 * j];
                t4[j] = kp + __shfl_xor_sync(FULLMASK, snd, 2);
            }
            float t2[2];
            #pragma unroll
            for (int j = 0; j < 2; ++j) {
                bool h = (lane & 1) != 0;
                float snd = h ? t4[2 * j] : t4[2 * j + 1];
                float kp  = h ? t4[2 * j + 1] : t4[2 * j];
                t2[j] = kp + __shfl_xor_sync(FULLMASK, snd, 1);
            }
            #pragma unroll
            for (int t = 0; t < 2; ++t) {
                int idx = t * 16 + bidx;        // value index in [0,32)
                int k = idx >> 1;
                int ci = k >> 2, mp = k & 3;
                int m = 2 * mp + (idx & 1);
                dot_s[wid][(ch * 7 + ci) * 8 + m] = t2[t];
            }
        }

        // ---- Pass B: reduce 32 values (ci 4..6 + l1) ----
        {
            float a[32];
            #pragma unroll
            for (int ci = 0; ci < 3; ++ci)
                #pragma unroll
                for (int mp = 0; mp < 4; ++mp)
                    upk(acc[4 + ci][mp], a[(ci * 4 + mp) * 2], a[(ci * 4 + mp) * 2 + 1]);
            a[24] = l1;
            #pragma unroll
            for (int j = 25; j < 32; ++j) a[j] = 0.0f;

            float t16[16];
            #pragma unroll
            for (int j = 0; j < 16; ++j) {
                bool h = (lane & 8) != 0;
                float snd = h ? a[2 * j] : a[2 * j + 1];
                float kp  = h ? a[2 * j + 1] : a[2 * j];
                t16[j] = kp + __shfl_xor_sync(FULLMASK, snd, 8);
            }
            float t8[8];
            #pragma unroll
            for (int j = 0; j < 8; ++j) {
                bool h = (lane & 4) != 0;
                float snd = h ? t16[2 * j] : t16[2 * j + 1];
                float kp  = h ? t16[2 * j + 1] : t16[2 * j];
                t8[j] = kp + __shfl_xor_sync(FULLMASK, snd, 4);
            }
            float t4[4];
            #pragma unroll
            for (int j = 0; j < 4; ++j) {
                bool h = (lane & 2) != 0;
                float snd = h ? t8[2 * j] : t8[2 * j + 1];
                float kp  = h ? t8[2 * j + 1] : t8[2 * j];
                t4[j] = kp + __shfl_xor_sync(FULLMASK, snd, 2);
            }
            float t2[2];
            #pragma unroll
            for (int j = 0; j < 2; ++j) {
                bool h = (lane & 1) != 0;
                float snd = h ? t4[2 * j] : t4[2 * j + 1];
                float kp  = h ? t4[2 * j + 1] : t4[2 * j];
                t2[j] = kp + __shfl_xor_sync(FULLMASK, snd, 1);
            }
            #pragma unroll
            for (int t = 0; t < 2; ++t) {
                int idx = t * 16 + bidx;
                if (idx < 24) {
                    int k = idx >> 1;
                    int ci = 4 + (k >> 2), mp = k & 3;
                    int m = 2 * mp + (idx & 1);
                    dot_s[wid][(ch * 7 + ci) * 8 + m] = t2[t];
                } else if (idx == 24) {
                    l1_s[wid][ch] = t2[t];
                }
            }
        }
        __syncwarp();

        // ---- epilogue (warp-local) ----
        const bool inc = lane < 14;
        float dmax = -FLT_MAX;
        if (inc) {
            #pragma unroll
            for (int m = 0; m < 8; ++m)
                dmax = fmaxf(dmax, dot_s[wid][lane * 8 + m]);
            dc_s[wid][lane] = dmax;
        }
        const unsigned pmask = __ballot_sync(FULLMASK, inc && (yv == 1));
        const unsigned nmask = (~pmask) & 0x3FFFu;
        const int npos = __popc(pmask);
        const int nneg = __popc(nmask);
        __syncwarp();

        float sloc = 0.0f, diag = 0.0f, row = 0.0f;
        if (inc && ((pmask >> lane) & 1)) {
            if (nneg > 0) {
                #pragma unroll
                for (int n = 0; n < 14; ++n)
                    if ((nmask >> n) & 1) sloc += softplus_f(dc_s[wid][n] - dmax);
            } else {
                sloc = softplus_f(-dmax);
            }
            diag = gram_s[lane * 15];
            #pragma unroll
            for (int c2 = 0; c2 < 14; ++c2)
                if ((pmask >> c2) & 1) row += gram_s[lane * 14 + c2];
        }
        #pragma unroll
        for (int o = 16; o; o >>= 1) {
            sloc += __shfl_xor_sync(FULLMASK, sloc, o);
            diag += __shfl_xor_sync(FULLMASK, diag, o);
            row  += __shfl_xor_sync(FULLMASK, row,  o);
        }
        if (lane == 0) {
            const float npf = (float)npos;
            float tv = 0.0f;
            if (npos > 1) tv = (diag - row / npf) / (npf - 1.0f);
            const float base = sloc / npf;
            const float l1t = l1_s[wid][0];
            wsum += 2.0f * (0.7f * (1.0f + tv) * base + 0.3f * l1t);
        }
    }

    // ---- block partial + in-kernel final reduction (last block) ----
    if (lane == 0) wpart[wid] = wsum;
    __syncthreads();
    if (tid == 0) {
        float bs = wpart[0] + wpart[1] + wpart[2] + wpart[3]
                 + wpart[4] + wpart[5] + wpart[6] + wpart[7];
        g_partials[blockIdx.x] = bs;
        __threadfence();
        unsigned old = atomicAdd(&g_counter, 1u);
        lastflag = (old == NBLK - 1) ? 1 : 0;
    }
    __syncthreads();
    if (lastflag && wid == 0) {
        float vsum = 0.0f;
        for (int k = lane; k < NBLK; k += 32) vsum += __ldcg(&g_partials[k]);
        #pragma unroll
        for (int o = 16; o; o >>= 1) vsum += __shfl_xor_sync(FULLMASK, vsum, o);
        if (lane == 0) {
            out[0] = vsum * (1.0f / 8192.0f);
            g_counter = 0;   // reset for next graph replay
        }
    }
}

extern "C" void kernel_launch(void* const* d_in, const int* in_sizes, int n_in,
                              void* d_out, int out_size) {
    const float* x = (const float*)d_in[0];
    const int*   y = (const int*)d_in[1];
    const float* w = (const float*)d_in[2];

    const int dyn_smem = 14 * WROW * (int)sizeof(float2);   // 57,792 B
    cudaFuncSetAttribute(main_kernel, cudaFuncAttributeMaxDynamicSharedMemorySize,
                         dyn_smem);
    main_kernel<<<NBLK, 256, dyn_smem>>>(x, y, w, (float*)d_out);
}